// round 16
// baseline (speedup 1.0000x reference)
#include <cuda_runtime.h>
#include <cuda_bf16.h>

// CopyMechanism (pointer-generator): gate + vocab scale + scatter.
// B=16, T=128, H=512, V=32000, S=400.
//
// R9: single fused kernel with in-kernel producer/consumer gate.
//  - memset node poisons g_pgen to 0xFF (NaN bits, impossible sigmoid output).
//  - tile-0 CTA of each row computes the gate and volatile-stores p_gen bits
//    (single word = data+flag, no fence needed).
//  - tiles 1-3 spin on the word (thread 0 + smem broadcast). Producer bid 4r
//    precedes consumer bids 4r+1..3; GB300 schedules CTAs in bid order, so a
//    resident consumer's producer is always resident-or-finished -> no deadlock.
//  - streaming scale + range-filtered scatter identical to the proven 82us K2.
//
// Inputs (metadata order):
//  0 context_vecs [B,T,H] f32,  1 hidden [B,T,H] f32,  2 trg_embs [B,T,H] f32
//  3 vocab_dists [B,T,V] f32,   4 attn_dists [B,T,S] f32, 5 src_ids [B,T,S] i32
//  6 pad_id (unused), 7 w_h [1,H], 8 w_s [1,H], 9 w_x_w [1,H], 10 w_x_b [1]
// output: [B,T,V] f32

#define HDIM 512
#define VDIM 32000
#define SDIM 400
#define NROWS 2048
#define NTHREADS 256
#define NWARPS (NTHREADS / 32)
#define TILES_PER_ROW 4
#define TILE_ELEMS (VDIM / TILES_PER_ROW)   // 8000 floats
#define TILE4 (TILE_ELEMS / 4)              // 2000 float4

#define SENTINEL 0xFFFFFFFFu   // NaN bit pattern; sigmoid output never has it

__device__ unsigned int g_pgen_bits[NROWS];

__global__ __launch_bounds__(NTHREADS)
void copy_mechanism_kernel(
    const float* __restrict__ ctx,
    const float* __restrict__ hid,
    const float* __restrict__ trg,
    const float* __restrict__ vocab,
    const float* __restrict__ attn,
    const int*   __restrict__ src_ids,
    const float* __restrict__ w_h,
    const float* __restrict__ w_s,
    const float* __restrict__ w_x,
    const float* __restrict__ w_b,
    float* __restrict__ out)
{
    const int row  = blockIdx.x >> 2;       // 0 .. NROWS-1
    const int tile = blockIdx.x & 3;        // quarter of the row
    const int tid  = threadIdx.x;
    const int lane = tid & 31;
    const int warp = tid >> 5;

    __shared__ float s_red[NWARPS];
    __shared__ float s_pgen;

    float p_gen;

    if (tile == 0) {
        // ---- Producer: compute gate for this row ----
        const float2* c2  = reinterpret_cast<const float2*>(ctx + (size_t)row * HDIM);
        const float2* h2  = reinterpret_cast<const float2*>(hid + (size_t)row * HDIM);
        const float2* t2  = reinterpret_cast<const float2*>(trg + (size_t)row * HDIM);
        const float2* wh2 = reinterpret_cast<const float2*>(w_h);
        const float2* ws2 = reinterpret_cast<const float2*>(w_s);
        const float2* wx2 = reinterpret_cast<const float2*>(w_x);

        // HDIM/2 = 256 float2 -> exactly one per thread
        float2 cv = c2[tid], hv = h2[tid], tv = t2[tid];
        float2 wh = wh2[tid], ws = ws2[tid], wx = wx2[tid];
        float acc = cv.x * wh.x + cv.y * wh.y
                  + hv.x * ws.x + hv.y * ws.y
                  + tv.x * wx.x + tv.y * wx.y;

        #pragma unroll
        for (int o = 16; o > 0; o >>= 1)
            acc += __shfl_down_sync(0xFFFFFFFFu, acc, o);
        if (lane == 0) s_red[warp] = acc;
        const float bias = w_b[0];
        __syncthreads();

        float logit = bias;
        #pragma unroll
        for (int w = 0; w < NWARPS; w++) logit += s_red[w];
        p_gen = 1.0f / (1.0f + __expf(-logit));

        if (tid == 0) {
            // Single-word publish: value doubles as readiness flag.
            *((volatile unsigned int*)&g_pgen_bits[row]) = __float_as_uint(p_gen);
        }
    } else {
        // ---- Consumer: wait for tile-0 CTA of this row ----
        if (tid == 0) {
            unsigned int v = *((volatile unsigned int*)&g_pgen_bits[row]);
            while (v == SENTINEL) {
                __nanosleep(64);
                v = *((volatile unsigned int*)&g_pgen_bits[row]);
            }
            s_pgen = __uint_as_float(v);
        }
        __syncthreads();
        p_gen = s_pgen;
    }

    const float one_minus = 1.0f - p_gen;

    // ---- Streaming scale over this quarter (proven K2 body) ----
    {
        const float4* v4 = reinterpret_cast<const float4*>(vocab + (size_t)row * VDIM)
                         + tile * TILE4;
        float4* o4 = reinterpret_cast<float4*>(out + (size_t)row * VDIM)
                   + tile * TILE4;
        #pragma unroll 4
        for (int i = tid; i < TILE4; i += NTHREADS) {
            float4 v = v4[i];
            v.x *= p_gen; v.y *= p_gen; v.z *= p_gen; v.w *= p_gen;
            o4[i] = v;
        }
    }

    __syncthreads();   // tile fully written before scatter RMW into it

    // ---- Range-filtered scatter-add into THIS tile only ----
    {
        const int lo = tile * TILE_ELEMS;
        const int hi = lo + TILE_ELEMS;
        const float* a   = attn + (size_t)row * SDIM;
        const int*   ids = src_ids + (size_t)row * SDIM;
        float* orow = out + (size_t)row * VDIM;
        for (int j = tid; j < SDIM; j += NTHREADS) {
            int id = ids[j];
            if (id >= lo && id < hi)
                atomicAdd(&orow[id], one_minus * a[j]);
        }
    }
}

extern "C" void kernel_launch(void* const* d_in, const int* in_sizes, int n_in,
                              void* d_out, int out_size) {
    const float* ctx   = (const float*)d_in[0];
    const float* hid   = (const float*)d_in[1];
    const float* trg   = (const float*)d_in[2];
    const float* vocab = (const float*)d_in[3];
    const float* attn  = (const float*)d_in[4];
    const int*   sid   = (const int*)d_in[5];
    const float* w_h   = (const float*)d_in[7];
    const float* w_s   = (const float*)d_in[8];
    const float* w_x   = (const float*)d_in[9];
    const float* w_b   = (const float*)d_in[10];
    float* out = (float*)d_out;

    // Poison the gate scratch each launch (graph-capturable, no alloc).
    void* pgen_ptr = nullptr;
    cudaGetSymbolAddress(&pgen_ptr, g_pgen_bits);
    cudaMemsetAsync(pgen_ptr, 0xFF, NROWS * sizeof(unsigned int), 0);

    copy_mechanism_kernel<<<NROWS * TILES_PER_ROW, NTHREADS>>>(
        ctx, hid, trg, vocab, attn, sid, w_h, w_s, w_x, w_b, out);
}